// round 4
// baseline (speedup 1.0000x reference)
#include <cuda_runtime.h>

#define D        128
#define TM       128
#define NTH      256
#define TSTEPS   100

typedef unsigned long long ull;

struct Small {
    float xs[TM];        // current x per row
    float nzs[TM];       // noise for current step
    float w1x[D];        // W1 row 128
    float w1t[D];        // W1 row 129
    float b2s[D];
    float w3s[D];
    float b1s[D];
    float tembs[TSTEPS];
    float cA[TSTEPS];    // 1/sqrt(alpha_t)
    float cB[TSTEPS];    // beta_t / sqrt(1-acp_t)
    float cC[TSTEPS];    // sqrt(beta_t), 0 at t==0
    float b3v;
};

__device__ __forceinline__ float silu_f(float v) {
    // x * sigmoid(x) = x / (1 + e^{-x}); EX2 + RCP MUFUs, ~2 ulp
    float e = __expf(-v);
    return __fdividef(v, 1.0f + e);
}

// packed f32x2 helpers (FFMA2 path: only reachable via PTX fma.rn.f32x2)
__device__ __forceinline__ ull spl2(float x) {
    ull r;
    asm("mov.b64 %0, {%1, %1};" : "=l"(r) : "r"(__float_as_uint(x)));
    return r;
}
__device__ __forceinline__ void ffma2(ull& d, ull a, ull b) {
    asm("fma.rn.f32x2 %0, %1, %2, %0;" : "+l"(d) : "l"(a), "l"(b));
}
__device__ __forceinline__ float2 upk2(ull v) {
    unsigned lo, hi;
    asm("mov.b64 {%0, %1}, %2;" : "=r"(lo), "=r"(hi) : "l"(v));
    return make_float2(__uint_as_float(lo), __uint_as_float(hi));
}

extern "C" __global__ void __launch_bounds__(NTH, 1)
diff_kernel(const float* __restrict__ gctx,
            const float* __restrict__ gx0,
            const float* __restrict__ gnoise,
            const float* __restrict__ gW1,
            const float* __restrict__ gb1,
            const float* __restrict__ gW2,
            const float* __restrict__ gb2,
            const float* __restrict__ gW3,
            const float* __restrict__ gb3,
            const float* __restrict__ gtemb,
            float* __restrict__ gout,
            int B)
{
    extern __shared__ float sm[];
    float* Ws  = sm;             // [k][j]  W1[:128] during prologue, W2 afterwards (64KB)
    float* C1s = sm + D * D;     // [k][r]  context@W1[:128] + b1, k-major       (64KB)
    float* H1s = sm + 2 * D * D; // [k][r]  h1 per step (ctx^T during prologue)  (64KB)
    Small* S   = (Small*)(sm + 3 * D * D);

    const int tid = threadIdx.x;
    const int rowBase = blockIdx.x * TM;
    const int tc = tid & 15;          // col group  (8 cols)
    const int tr = tid >> 4;          // row group  (8 rows)
    const int r0 = tr * 8;
    const int j0 = tc * 8;

    // ---- stage W1[0:128,:] into Ws; small arrays ----
    for (int i = tid; i < D * D / 4; i += NTH)
        ((float4*)Ws)[i] = ((const float4*)gW1)[i];
    if (tid < D) {
        S->w1x[tid] = gW1[D * D + tid];
        S->w1t[tid] = gW1[D * D + D + tid];
        S->b1s[tid] = gb1[tid];
        S->b2s[tid] = gb2[tid];
        S->w3s[tid] = gW3[tid];
        S->xs[tid]  = gx0[rowBase + tid];
    } else if (tid < D + TSTEPS) {
        S->tembs[tid - D] = gtemb[tid - D];
    }
    if (tid == 0) {
        S->b3v = gb3[0];
        float acp = 1.0f;
        for (int t = 0; t < TSTEPS; ++t) {
            float beta  = 1e-4f + (0.02f - 1e-4f) * ((float)t * (1.0f / 99.0f));
            float alpha = 1.0f - beta;
            acp *= alpha;
            S->cA[t] = 1.0f / sqrtf(alpha);
            S->cB[t] = beta / sqrtf(1.0f - acp);
            S->cC[t] = (t > 0) ? sqrtf(beta) : 0.0f;
        }
    }

    // ---- transpose context tile into H1s[d][r] (one-time; STS conflicts OK) ----
    for (int i = tid; i < D * TM / 4; i += NTH) {
        int r  = i >> 5;            // 0..127
        int d4 = (i & 31) << 2;     // 0,4,...,124
        float4 v = *(const float4*)&gctx[(size_t)(rowBase + r) * D + d4];
        H1s[(d4 + 0) * TM + r] = v.x;
        H1s[(d4 + 1) * TM + r] = v.y;
        H1s[(d4 + 2) * TM + r] = v.z;
        H1s[(d4 + 3) * TM + r] = v.w;
    }
    __syncthreads();

    // ---- prologue GEMM: C1s[k][r] = sum_d ctx[r][d] * W1[d][k] + b1[k] ----
    {
        float acc[8][8];
#pragma unroll
        for (int a = 0; a < 8; ++a)
#pragma unroll
            for (int b = 0; b < 8; ++b) acc[a][b] = 0.0f;

#pragma unroll 4
        for (int d = 0; d < D; ++d) {
            float4 a0 = *(const float4*)&H1s[d * TM + r0];
            float4 a1 = *(const float4*)&H1s[d * TM + r0 + 4];
            float4 w0 = *(const float4*)&Ws[d * D + j0];
            float4 w1 = *(const float4*)&Ws[d * D + j0 + 4];
            float av[8] = {a0.x, a0.y, a0.z, a0.w, a1.x, a1.y, a1.z, a1.w};
            float bv[8] = {w0.x, w0.y, w0.z, w0.w, w1.x, w1.y, w1.z, w1.w};
#pragma unroll
            for (int a = 0; a < 8; ++a)
#pragma unroll
                for (int b = 0; b < 8; ++b)
                    acc[a][b] = fmaf(av[a], bv[b], acc[a][b]);
        }
#pragma unroll
        for (int b = 0; b < 8; ++b) {
            float bias = S->b1s[j0 + b];
#pragma unroll
            for (int a = 0; a < 8; ++a)
                C1s[(j0 + b) * TM + r0 + a] = acc[a][b] + bias;
        }
    }
    __syncthreads();

    // ---- overwrite Ws with W2 ----
    for (int i = tid; i < D * D / 4; i += NTH)
        ((float4*)Ws)[i] = ((const float4*)gW2)[i];
    __syncthreads();

    // ---- time loop: t = 99 .. 0, scan index it pairs with noise[it] ----
    for (int it = 0; it < TSTEPS; ++it) {
        const int t = TSTEPS - 1 - it;
        const float temb = S->tembs[t];

        // phase 1: H1s[k][r] = silu(C1 + x*w1x + temb*w1t)
        // per i: each warp owns one k (broadcast), lanes cover all 128 r — conflict-free
#pragma unroll
        for (int i = 0; i < (D * TM / 4) / NTH; ++i) {   // 16 iters
            int idx = i * NTH + tid;
            int k   = idx >> 5;
            int r4  = (idx & 31) << 2;
            float a  = S->w1x[k];
            float bt = S->w1t[k] * temb;
            float4 c  = *(const float4*)&C1s[k * TM + r4];
            float4 xv = *(const float4*)&S->xs[r4];
            float4 h;
            h.x = silu_f(fmaf(xv.x, a, c.x) + bt);
            h.y = silu_f(fmaf(xv.y, a, c.y) + bt);
            h.z = silu_f(fmaf(xv.z, a, c.z) + bt);
            h.w = silu_f(fmaf(xv.w, a, c.w) + bt);
            *(float4*)&H1s[k * TM + r4] = h;
        }
        // prefetch this step's noise (consumed ~16K cycles later, latency hidden)
        if (tid < TM)
            S->nzs[tid] = gnoise[(size_t)it * (size_t)B + rowBase + tid];
        __syncthreads();

        // phase 2: 128x128x128 GEMM via packed f32x2 FMA.
        // acc[a][b]: row pair (r0+2a, r0+2a+1) x col (j0+b)
        ull acc[4][8];
#pragma unroll
        for (int a = 0; a < 4; ++a)
#pragma unroll
            for (int b = 0; b < 8; ++b) acc[a][b] = 0ull;

#pragma unroll 8
        for (int k = 0; k < D; ++k) {
            // 8 row values as 4 packed f32x2 (direct LDS.128, no packing movs)
            ulonglong2 aA = *(const ulonglong2*)&H1s[k * TM + r0];
            ulonglong2 aB = *(const ulonglong2*)&H1s[k * TM + r0 + 4];
            float4 w0 = *(const float4*)&Ws[k * D + j0];
            float4 w1 = *(const float4*)&Ws[k * D + j0 + 4];
            ull av[4] = {aA.x, aA.y, aB.x, aB.y};
            ull bs[8] = {spl2(w0.x), spl2(w0.y), spl2(w0.z), spl2(w0.w),
                         spl2(w1.x), spl2(w1.y), spl2(w1.z), spl2(w1.w)};
#pragma unroll
            for (int a = 0; a < 4; ++a)
#pragma unroll
                for (int b = 0; b < 8; ++b)
                    ffma2(acc[a][b], av[a], bs[b]);
        }

        // epilogue: h2 = silu(acc + b2); partial pred = sum_j h2 * W3[j]
        float2 pr[4];
#pragma unroll
        for (int a = 0; a < 4; ++a) { pr[a].x = 0.0f; pr[a].y = 0.0f; }
#pragma unroll
        for (int b = 0; b < 8; ++b) {
            float w3   = S->w3s[j0 + b];
            float bias = S->b2s[j0 + b];
#pragma unroll
            for (int a = 0; a < 4; ++a) {
                float2 v = upk2(acc[a][b]);
                pr[a].x = fmaf(silu_f(v.x + bias), w3, pr[a].x);
                pr[a].y = fmaf(silu_f(v.y + bias), w3, pr[a].y);
            }
        }
        // butterfly reduce across the 16 lanes sharing a row group (stays in-warp)
#pragma unroll
        for (int s = 1; s < 16; s <<= 1) {
#pragma unroll
            for (int a = 0; a < 4; ++a) {
                pr[a].x += __shfl_xor_sync(0xffffffffu, pr[a].x, s);
                pr[a].y += __shfl_xor_sync(0xffffffffu, pr[a].y, s);
            }
        }
        // x update (one writer per row group)
        if (tc == 0) {
            float cAv = S->cA[t], cBv = S->cB[t], cCv = S->cC[t];
            float b3v = S->b3v;
#pragma unroll
            for (int a = 0; a < 4; ++a) {
                int r = r0 + a * 2;
                float p0 = pr[a].x + b3v;
                float p1 = pr[a].y + b3v;
                S->xs[r]     = (S->xs[r]     - cBv * p0) * cAv + cCv * S->nzs[r];
                S->xs[r + 1] = (S->xs[r + 1] - cBv * p1) * cAv + cCv * S->nzs[r + 1];
            }
        }
        __syncthreads();
    }

    if (tid < TM)
        gout[rowBase + tid] = S->xs[tid];
}

extern "C" void kernel_launch(void* const* d_in, const int* in_sizes, int n_in,
                              void* d_out, int out_size)
{
    const float* ctx = (const float*)d_in[0];
    const float* x0  = (const float*)d_in[1];
    const float* nz  = (const float*)d_in[2];
    const float* W1  = (const float*)d_in[3];
    const float* b1  = (const float*)d_in[4];
    const float* W2  = (const float*)d_in[5];
    const float* b2  = (const float*)d_in[6];
    const float* W3  = (const float*)d_in[7];
    const float* b3  = (const float*)d_in[8];
    const float* te  = (const float*)d_in[9];
    float* out = (float*)d_out;

    const int B = in_sizes[1];                 // 262144 rows (x_init count)
    const size_t smem = 3 * D * D * sizeof(float) + sizeof(Small);  // ~202 KB

    cudaFuncSetAttribute(diff_kernel,
                         cudaFuncAttributeMaxDynamicSharedMemorySize,
                         (int)smem);

    diff_kernel<<<B / TM, NTH, smem>>>(ctx, x0, nz, W1, b1, W2, b2, W3, b3, te,
                                       out, B);
}

// round 7
// speedup vs baseline: 2.5819x; 2.5819x over previous
#include <cuda_runtime.h>
#include <cuda_bf16.h>
#include <cstdint>

#define D        128
#define TM       128
#define NTH      256
#define TSTEPS   100

#define PADB     272            // bytes per bf16 tile row (136 bf16, ≡4 words mod 32)
#define TILE     (128 * PADB)   // 34816 B per 128x128 bf16 tile

// ---- dynamic smem byte offsets ----
#define OFF_C1    0                         // C1s [k][r] fp32, 64KB (ctx@W1+b1, step-invariant)
#define OFF_AHI   65536                     // h1 hi tile [m][k]
#define OFF_ALO   (OFF_AHI + TILE)          // h1 lo tile
#define OFF_BHI   (OFF_ALO + TILE)          // W2^T hi tile [n][k]
#define OFF_BLO   (OFF_BHI + TILE)          // W2^T lo tile
#define OFF_SMALL (OFF_BLO + TILE)          // 204800

struct Small {
    float xs[TM];
    float nzs[TM];
    float w1x[D], w1t[D], b1s[D], b2s[D], w3s[D];
    float tembs[TSTEPS], cA[TSTEPS], cB[TSTEPS], cC[TSTEPS];
    float predp[2][TM];
    float b3v;
};

__device__ __forceinline__ uint32_t smem_u32(const void* p) {
    uint32_t a;
    asm("{ .reg .u64 t; cvta.to.shared.u64 t, %1; cvt.u32.u64 %0, t; }" : "=r"(a) : "l"(p));
    return a;
}
__device__ __forceinline__ float silu_f(float v) {
    float e = __expf(-v);
    return __fdividef(v, 1.0f + e);
}
__device__ __forceinline__ void ldm4(uint32_t* r, uint32_t addr) {
    asm volatile("ldmatrix.sync.aligned.m8n8.x4.shared.b16 {%0,%1,%2,%3}, [%4];"
                 : "=r"(r[0]), "=r"(r[1]), "=r"(r[2]), "=r"(r[3]) : "r"(addr));
}
__device__ __forceinline__ void mma16816(float* c, const uint32_t* a, const uint32_t* b) {
    asm volatile(
        "mma.sync.aligned.m16n8k16.row.col.f32.bf16.bf16.f32 "
        "{%0,%1,%2,%3}, {%4,%5,%6,%7}, {%8,%9}, {%0,%1,%2,%3};"
        : "+f"(c[0]), "+f"(c[1]), "+f"(c[2]), "+f"(c[3])
        : "r"(a[0]), "r"(a[1]), "r"(a[2]), "r"(a[3]), "r"(b[0]), "r"(b[1]));
}

extern "C" __global__ void __launch_bounds__(NTH, 1)
diff_kernel(const float* __restrict__ gctx,
            const float* __restrict__ gx0,
            const float* __restrict__ gnoise,
            const float* __restrict__ gW1,
            const float* __restrict__ gb1,
            const float* __restrict__ gW2,
            const float* __restrict__ gb2,
            const float* __restrict__ gW3,
            const float* __restrict__ gb3,
            const float* __restrict__ gtemb,
            float* __restrict__ gout,
            int B)
{
    extern __shared__ char smb[];
    float* C1s = (float*)(smb + OFF_C1);
    Small* S   = (Small*)(smb + OFF_SMALL);

    const int tid = threadIdx.x;
    const int w   = tid >> 5;
    const int l   = tid & 31;
    const int rowBase = blockIdx.x * TM;

    // ---- stage W1[0:128,:] fp32 into B region, ctx^T into A region; scalars ----
    float* Ws   = (float*)(smb + OFF_BHI);
    float* ctxT = (float*)(smb + OFF_AHI);
    for (int i = tid; i < D * D / 4; i += NTH)
        ((float4*)Ws)[i] = ((const float4*)gW1)[i];
    if (tid < D) {
        S->w1x[tid] = gW1[D * D + tid];
        S->w1t[tid] = gW1[D * D + D + tid];
        S->b1s[tid] = gb1[tid];
        S->b2s[tid] = gb2[tid];
        S->w3s[tid] = gW3[tid];
        S->xs[tid]  = gx0[rowBase + tid];
    } else if (tid < D + TSTEPS) {
        S->tembs[tid - D] = gtemb[tid - D];
    }
    if (tid == 0) {
        S->b3v = gb3[0];
        float acp = 1.0f;
        for (int t = 0; t < TSTEPS; ++t) {
            float beta  = 1e-4f + (0.02f - 1e-4f) * ((float)t * (1.0f / 99.0f));
            float alpha = 1.0f - beta;
            acp *= alpha;
            S->cA[t] = 1.0f / sqrtf(alpha);
            S->cB[t] = beta / sqrtf(1.0f - acp);
            S->cC[t] = (t > 0) ? sqrtf(beta) : 0.0f;
        }
    }
    for (int i = tid; i < D * TM / 4; i += NTH) {
        int r  = i >> 5;
        int d4 = (i & 31) << 2;
        float4 v = *(const float4*)&gctx[(size_t)(rowBase + r) * D + d4];
        ctxT[(d4 + 0) * TM + r] = v.x;
        ctxT[(d4 + 1) * TM + r] = v.y;
        ctxT[(d4 + 2) * TM + r] = v.z;
        ctxT[(d4 + 3) * TM + r] = v.w;
    }
    __syncthreads();

    // ---- prologue GEMM (fp32 SIMT, once): C1s[k][r] = ctx@W1 + b1 ----
    {
        const int tc = tid & 15, tr = tid >> 4;
        const int r0 = tr * 8, j0 = tc * 8;
        float acc[8][8];
#pragma unroll
        for (int a = 0; a < 8; ++a)
#pragma unroll
            for (int b = 0; b < 8; ++b) acc[a][b] = 0.0f;
#pragma unroll 4
        for (int d = 0; d < D; ++d) {
            float4 a0 = *(const float4*)&ctxT[d * TM + r0];
            float4 a1 = *(const float4*)&ctxT[d * TM + r0 + 4];
            float4 w0 = *(const float4*)&Ws[d * D + j0];
            float4 w1 = *(const float4*)&Ws[d * D + j0 + 4];
            float av[8] = {a0.x, a0.y, a0.z, a0.w, a1.x, a1.y, a1.z, a1.w};
            float bv[8] = {w0.x, w0.y, w0.z, w0.w, w1.x, w1.y, w1.z, w1.w};
#pragma unroll
            for (int a = 0; a < 8; ++a)
#pragma unroll
                for (int b = 0; b < 8; ++b)
                    acc[a][b] = fmaf(av[a], bv[b], acc[a][b]);
        }
#pragma unroll
        for (int b = 0; b < 8; ++b) {
            float bias = S->b1s[j0 + b];
#pragma unroll
            for (int a = 0; a < 8; ++a)
                C1s[(j0 + b) * TM + r0 + a] = acc[a][b] + bias;
        }
    }
    __syncthreads();

    // ---- build B tiles once: Bt[n][k] = W2[k][n], hi/lo bf16, stride 272B ----
    for (int idx = tid; idx < D * D; idx += NTH) {
        int k = idx >> 7, n = idx & 127;
        float wv = gW2[idx];
        __nv_bfloat16 wh = __float2bfloat16(wv);
        __nv_bfloat16 wl = __float2bfloat16(wv - __bfloat162float(wh));
        int off = n * PADB + k * 2;
        *(__nv_bfloat16*)(smb + OFF_BHI + off) = wh;
        *(__nv_bfloat16*)(smb + OFF_BLO + off) = wl;
    }
    __syncthreads();

    // ---- per-thread roles ----
    // phase 1: row r, k-half kh, k-pair rotation for conflict-free stores
    const int r1  = (w & 3) * 32 + l;
    const int kh  = (w >> 2) * 64;
    const int rot = l >> 3;
    char* Ahi = smb + OFF_AHI;
    char* Alo = smb + OFF_ALO;

    // phase 2: warp tile = 32 rows (mq) x 64 cols (nq)
    const int mq = w & 3;
    const int nq = w >> 2;
    const uint32_t aBase = smem_u32(smb + OFF_AHI)
                         + (uint32_t)(mq * 32 + (l & 15)) * PADB + (uint32_t)(l >> 4) * 16;
    const uint32_t bBase = smem_u32(smb + OFF_BHI)
                         + (uint32_t)(nq * 64 + (l & 15)) * PADB + (uint32_t)(l >> 4) * 16;

    // hoist epilogue per-lane constants: cols c(n8) = nq*64 + n8*8 + (l%4)*2 + {0,1}
    float b2v0[8], b2v1[8], w3v0[8], w3v1[8];
#pragma unroll
    for (int n8 = 0; n8 < 8; ++n8) {
        int c = nq * 64 + n8 * 8 + (l & 3) * 2;
        b2v0[n8] = S->b2s[c];     b2v1[n8] = S->b2s[c + 1];
        w3v0[n8] = S->w3s[c];     w3v1[n8] = S->w3s[c + 1];
    }

    for (int it = 0; it < TSTEPS; ++it) {
        const int t = TSTEPS - 1 - it;
        const float temb = S->tembs[t];
        const float xr = S->xs[r1];

        // ---- phase 1: h1 = silu(C1 + x*w1x + temb*w1t); hi/lo split -> A tiles ----
#pragma unroll 4
        for (int j = 0; j < 32; ++j) {
            int kp = (j + rot) & 31;
            int k  = kh + kp * 2;
            float h0 = silu_f(fmaf(xr, S->w1x[k],     C1s[k * TM + r1])       + temb * S->w1t[k]);
            float h1 = silu_f(fmaf(xr, S->w1x[k + 1], C1s[(k + 1) * TM + r1]) + temb * S->w1t[k + 1]);
            __nv_bfloat162 hv;
            hv.x = __float2bfloat16(h0);
            hv.y = __float2bfloat16(h1);
            __nv_bfloat162 lv = __floats2bfloat162_rn(h0 - __bfloat162float(hv.x),
                                                      h1 - __bfloat162float(hv.y));
            int off = r1 * PADB + k * 2;
            *(__nv_bfloat162*)(Ahi + off) = hv;
            *(__nv_bfloat162*)(Alo + off) = lv;
        }
        if (tid < TM)
            S->nzs[tid] = gnoise[(size_t)it * (size_t)B + rowBase + tid];
        __syncthreads();

        // ---- phase 2: out = Ahi*Bhi + Ahi*Blo + Alo*Bhi  (HMMA, reg accum) ----
        float acc[2][8][4];
#pragma unroll
        for (int mc = 0; mc < 2; ++mc)
#pragma unroll
            for (int n8 = 0; n8 < 8; ++n8)
#pragma unroll
                for (int q = 0; q < 4; ++q) acc[mc][n8][q] = 0.0f;

#pragma unroll
        for (int kc = 0; kc < 8; ++kc) {
            uint32_t bh[8][2], bl[8][2];
#pragma unroll
            for (int nb = 0; nb < 4; ++nb) {
                uint32_t q[4];
                ldm4(q, bBase + nb * 16 * PADB + kc * 32);
                bh[2 * nb][0] = q[0]; bh[2 * nb][1] = q[2];
                bh[2 * nb + 1][0] = q[1]; bh[2 * nb + 1][1] = q[3];
                ldm4(q, bBase + TILE + nb * 16 * PADB + kc * 32);
                bl[2 * nb][0] = q[0]; bl[2 * nb][1] = q[2];
                bl[2 * nb + 1][0] = q[1]; bl[2 * nb + 1][1] = q[3];
            }
#pragma unroll
            for (int mc = 0; mc < 2; ++mc) {
                uint32_t ah[4], al[4];
                ldm4(ah, aBase + mc * 16 * PADB + kc * 32);
                ldm4(al, aBase + TILE + mc * 16 * PADB + kc * 32);
#pragma unroll
                for (int n8 = 0; n8 < 8; ++n8) {
                    mma16816(acc[mc][n8], ah, bh[n8]);
                    mma16816(acc[mc][n8], ah, bl[n8]);
                    mma16816(acc[mc][n8], al, bh[n8]);
                }
            }
        }

        // ---- epilogue: silu(out+b2)·w3, row-sum; quad shfl reduce ----
        float rs[2][2];
        rs[0][0] = rs[0][1] = rs[1][0] = rs[1][1] = 0.0f;
#pragma unroll
        for (int mc = 0; mc < 2; ++mc)
#pragma unroll
            for (int n8 = 0; n8 < 8; ++n8) {
                rs[mc][0] = fmaf(silu_f(acc[mc][n8][0] + b2v0[n8]), w3v0[n8], rs[mc][0]);
                rs[mc][0] = fmaf(silu_f(acc[mc][n8][1] + b2v1[n8]), w3v1[n8], rs[mc][0]);
                rs[mc][1] = fmaf(silu_f(acc[mc][n8][2] + b2v0[n8]), w3v0[n8], rs[mc][1]);
                rs[mc][1] = fmaf(silu_f(acc[mc][n8][3] + b2v1[n8]), w3v1[n8], rs[mc][1]);
            }
#pragma unroll
        for (int s = 1; s < 4; s <<= 1) {
#pragma unroll
            for (int mc = 0; mc < 2; ++mc) {
                rs[mc][0] += __shfl_xor_sync(0xffffffffu, rs[mc][0], s);
                rs[mc][1] += __shfl_xor_sync(0xffffffffu, rs[mc][1], s);
            }
        }
        if ((l & 3) == 0) {
            int rq = l >> 2;
#pragma unroll
            for (int mc = 0; mc < 2; ++mc) {
                S->predp[nq][mq * 32 + mc * 16 + rq]     = rs[mc][0];
                S->predp[nq][mq * 32 + mc * 16 + 8 + rq] = rs[mc][1];
            }
        }
        __syncthreads();

        // ---- x update ----
        if (tid < TM) {
            float p = S->predp[0][tid] + S->predp[1][tid] + S->b3v;
            S->xs[tid] = (S->xs[tid] - S->cB[t] * p) * S->cA[t] + S->cC[t] * S->nzs[tid];
        }
        __syncthreads();
    }

    if (tid < TM)
        gout[rowBase + tid] = S->xs[tid];
}

extern "C" void kernel_launch(void* const* d_in, const int* in_sizes, int n_in,
                              void* d_out, int out_size)
{
    const float* ctx = (const float*)d_in[0];
    const float* x0  = (const float*)d_in[1];
    const float* nz  = (const float*)d_in[2];
    const float* W1  = (const float*)d_in[3];
    const float* b1  = (const float*)d_in[4];
    const float* W2  = (const float*)d_in[5];
    const float* b2  = (const float*)d_in[6];
    const float* W3  = (const float*)d_in[7];
    const float* b3  = (const float*)d_in[8];
    const float* te  = (const float*)d_in[9];
    float* out = (float*)d_out;

    const int B = in_sizes[1];
    const size_t smem = OFF_SMALL + sizeof(Small);   // ~211 KB

    cudaFuncSetAttribute(diff_kernel,
                         cudaFuncAttributeMaxDynamicSharedMemorySize,
                         (int)smem);

    diff_kernel<<<B / TM, NTH, smem>>>(ctx, x0, nz, W1, b1, W2, b2, W3, b3, te,
                                       out, B);
}

// round 8
// speedup vs baseline: 3.3803x; 1.3092x over previous
#include <cuda_runtime.h>
#include <cuda_bf16.h>
#include <cstdint>

#define D        128
#define TM       128
#define NTH      512
#define TSTEPS   100

#define PADB     272            // bytes per bf16 tile row (136 bf16, ≡4 words mod 32)
#define TILE     (128 * PADB)   // 34816 B per 128x128 bf16 tile

// ---- dynamic smem byte offsets ----
#define OFF_C1    0                         // C1s [k][r] fp32, 64KB (ctx@W1+b1, step-invariant)
#define OFF_AHI   65536                     // h1 hi tile [m][k]
#define OFF_ALO   (OFF_AHI + TILE)          // h1 lo tile
#define OFF_BHI   (OFF_ALO + TILE)          // W2^T hi tile [n][k]
#define OFF_BLO   (OFF_BHI + TILE)          // W2^T lo tile
#define OFF_SMALL (OFF_BLO + TILE)

struct Small {
    float xs[TM];
    float nzs[TM];
    float w1x[D], w1t[D], b1s[D], b2s[D], w3s[D];
    float tembs[TSTEPS], cA[TSTEPS], cB[TSTEPS], cC[TSTEPS];
    float predp[4][TM];
    float b3v;
};

__device__ __forceinline__ uint32_t smem_u32(const void* p) {
    uint32_t a;
    asm("{ .reg .u64 t; cvta.to.shared.u64 t, %1; cvt.u32.u64 %0, t; }" : "=r"(a) : "l"(p));
    return a;
}
// silu = x*sigmoid(x) = 0.5x + 0.5x*tanh(x/2): ONE MUFU (tanh) instead of EX2+RCP
__device__ __forceinline__ float silu_f(float v) {
    float th, hv = 0.5f * v;
    asm("tanh.approx.f32 %0, %1;" : "=f"(th) : "f"(hv));
    return fmaf(hv, th, hv);
}
__device__ __forceinline__ void ldm4(uint32_t* r, uint32_t addr) {
    asm volatile("ldmatrix.sync.aligned.m8n8.x4.shared.b16 {%0,%1,%2,%3}, [%4];"
                 : "=r"(r[0]), "=r"(r[1]), "=r"(r[2]), "=r"(r[3]) : "r"(addr));
}
__device__ __forceinline__ void mma16816(float* c, const uint32_t* a, const uint32_t* b) {
    asm volatile(
        "mma.sync.aligned.m16n8k16.row.col.f32.bf16.bf16.f32 "
        "{%0,%1,%2,%3}, {%4,%5,%6,%7}, {%8,%9}, {%0,%1,%2,%3};"
        : "+f"(c[0]), "+f"(c[1]), "+f"(c[2]), "+f"(c[3])
        : "r"(a[0]), "r"(a[1]), "r"(a[2]), "r"(a[3]), "r"(b[0]), "r"(b[1]));
}

extern "C" __global__ void __launch_bounds__(NTH, 1)
diff_kernel(const float* __restrict__ gctx,
            const float* __restrict__ gx0,
            const float* __restrict__ gnoise,
            const float* __restrict__ gW1,
            const float* __restrict__ gb1,
            const float* __restrict__ gW2,
            const float* __restrict__ gb2,
            const float* __restrict__ gW3,
            const float* __restrict__ gb3,
            const float* __restrict__ gtemb,
            float* __restrict__ gout,
            int B)
{
    extern __shared__ char smb[];
    float* C1s = (float*)(smb + OFF_C1);
    Small* S   = (Small*)(smb + OFF_SMALL);

    const int tid = threadIdx.x;
    const int w   = tid >> 5;
    const int l   = tid & 31;
    const int rowBase = blockIdx.x * TM;

    // ---- stage W1[0:128,:] fp32 into B region, ctx^T into A region; scalars ----
    float* Ws   = (float*)(smb + OFF_BHI);   // 64KB fp32 scratch (pre-tile)
    float* ctxT = (float*)(smb + OFF_AHI);   // 64KB fp32 scratch (pre-tile)
    for (int i = tid; i < D * D / 4; i += NTH)
        ((float4*)Ws)[i] = ((const float4*)gW1)[i];
    if (tid < D) {
        S->w1x[tid] = gW1[D * D + tid];
        S->w1t[tid] = gW1[D * D + D + tid];
        S->b1s[tid] = gb1[tid];
        S->b2s[tid] = gb2[tid];
        S->w3s[tid] = gW3[tid];
        S->xs[tid]  = gx0[rowBase + tid];
    } else if (tid < D + TSTEPS) {
        S->tembs[tid - D] = gtemb[tid - D];
    }
    if (tid == 0) {
        S->b3v = gb3[0];
        float acp = 1.0f;
        for (int t = 0; t < TSTEPS; ++t) {
            float beta  = 1e-4f + (0.02f - 1e-4f) * ((float)t * (1.0f / 99.0f));
            float alpha = 1.0f - beta;
            acp *= alpha;
            S->cA[t] = 1.0f / sqrtf(alpha);
            S->cB[t] = beta / sqrtf(1.0f - acp);
            S->cC[t] = (t > 0) ? sqrtf(beta) : 0.0f;
        }
    }
    for (int i = tid; i < D * TM / 4; i += NTH) {
        int r  = i >> 5;
        int d4 = (i & 31) << 2;
        float4 v = *(const float4*)&gctx[(size_t)(rowBase + r) * D + d4];
        ctxT[(d4 + 0) * TM + r] = v.x;
        ctxT[(d4 + 1) * TM + r] = v.y;
        ctxT[(d4 + 2) * TM + r] = v.z;
        ctxT[(d4 + 3) * TM + r] = v.w;
    }
    __syncthreads();

    // ---- prologue GEMM (fp32 SIMT, once): C1s[k][r] = ctx@W1 + b1 (first 256 thr) ----
    if (tid < 256) {
        const int tc = tid & 15, tr = tid >> 4;
        const int r0 = tr * 8, j0 = tc * 8;
        float acc[8][8];
#pragma unroll
        for (int a = 0; a < 8; ++a)
#pragma unroll
            for (int b = 0; b < 8; ++b) acc[a][b] = 0.0f;
#pragma unroll 4
        for (int d = 0; d < D; ++d) {
            float4 a0 = *(const float4*)&ctxT[d * TM + r0];
            float4 a1 = *(const float4*)&ctxT[d * TM + r0 + 4];
            float4 w0 = *(const float4*)&Ws[d * D + j0];
            float4 w1 = *(const float4*)&Ws[d * D + j0 + 4];
            float av[8] = {a0.x, a0.y, a0.z, a0.w, a1.x, a1.y, a1.z, a1.w};
            float bv[8] = {w0.x, w0.y, w0.z, w0.w, w1.x, w1.y, w1.z, w1.w};
#pragma unroll
            for (int a = 0; a < 8; ++a)
#pragma unroll
                for (int b = 0; b < 8; ++b)
                    acc[a][b] = fmaf(av[a], bv[b], acc[a][b]);
        }
#pragma unroll
        for (int b = 0; b < 8; ++b) {
            float bias = S->b1s[j0 + b];
#pragma unroll
            for (int a = 0; a < 8; ++a)
                C1s[(j0 + b) * TM + r0 + a] = acc[a][b] + bias;
        }
    }
    __syncthreads();

    // ---- build B tiles once: Bt[n][k] = W2[k][n], hi/lo bf16, stride 272B ----
    for (int idx = tid; idx < D * D; idx += NTH) {
        int k = idx >> 7, n = idx & 127;
        float wv = gW2[idx];
        __nv_bfloat16 wh = __float2bfloat16(wv);
        __nv_bfloat16 wl = __float2bfloat16(wv - __bfloat162float(wh));
        int off = n * PADB + k * 2;
        *(__nv_bfloat16*)(smb + OFF_BHI + off) = wh;
        *(__nv_bfloat16*)(smb + OFF_BLO + off) = wl;
    }
    __syncthreads();

    // ---- per-thread roles ----
    // phase 1: 4 threads per row; thread owns row r1, 16 k-pairs starting at kh
    const int r1  = tid & 127;
    const int kh  = (tid >> 7) << 5;     // 0,32,64,96
    const int rot = l >> 3;              // conflict-free store rotation
    char* Ahi = smb + OFF_AHI;
    char* Alo = smb + OFF_ALO;

    // phase 2: 4x4 warp grid, each warp 32 rows x 32 cols
    const int mq = w & 3;
    const int nq = w >> 2;
    const uint32_t aBase = smem_u32(smb + OFF_AHI)
                         + (uint32_t)(mq * 32 + (l & 15)) * PADB + (uint32_t)(l >> 4) * 16;
    const uint32_t bBase = smem_u32(smb + OFF_BHI)
                         + (uint32_t)(nq * 32 + (l & 15)) * PADB + (uint32_t)(l >> 4) * 16;

    // hoisted epilogue per-lane constants: cols c(n8) = nq*32 + n8*8 + (l%4)*2 + {0,1}
    float b2v0[4], b2v1[4], w3v0[4], w3v1[4];
#pragma unroll
    for (int n8 = 0; n8 < 4; ++n8) {
        int c = nq * 32 + n8 * 8 + (l & 3) * 2;
        b2v0[n8] = S->b2s[c];     b2v1[n8] = S->b2s[c + 1];
        w3v0[n8] = S->w3s[c];     w3v1[n8] = S->w3s[c + 1];
    }

    for (int it = 0; it < TSTEPS; ++it) {
        const int t = TSTEPS - 1 - it;
        const float temb = S->tembs[t];
        const float xr = S->xs[r1];

        // ---- phase 1: h1 = silu(C1 + x*w1x + temb*w1t); hi/lo split -> A tiles ----
#pragma unroll 4
        for (int j = 0; j < 16; ++j) {
            int kp = (j + rot) & 15;
            int k  = kh + kp * 2;
            float h0 = silu_f(fmaf(xr, S->w1x[k],     C1s[k * TM + r1])       + temb * S->w1t[k]);
            float h1 = silu_f(fmaf(xr, S->w1x[k + 1], C1s[(k + 1) * TM + r1]) + temb * S->w1t[k + 1]);
            __nv_bfloat162 hv;
            hv.x = __float2bfloat16(h0);
            hv.y = __float2bfloat16(h1);
            __nv_bfloat162 lv = __floats2bfloat162_rn(h0 - __bfloat162float(hv.x),
                                                      h1 - __bfloat162float(hv.y));
            int off = r1 * PADB + k * 2;
            *(__nv_bfloat162*)(Ahi + off) = hv;
            *(__nv_bfloat162*)(Alo + off) = lv;
        }
        if (tid < TM)
            S->nzs[tid] = gnoise[(size_t)it * (size_t)B + rowBase + tid];
        __syncthreads();

        // ---- phase 2: out = Ahi*Bhi + Ahi*Blo + Alo*Bhi  (HMMA, reg accum) ----
        float acc[2][4][4];
#pragma unroll
        for (int mc = 0; mc < 2; ++mc)
#pragma unroll
            for (int n8 = 0; n8 < 4; ++n8)
#pragma unroll
                for (int q = 0; q < 4; ++q) acc[mc][n8][q] = 0.0f;

#pragma unroll
        for (int kc = 0; kc < 8; ++kc) {
            uint32_t bh[4][2], bl[4][2];
#pragma unroll
            for (int nb = 0; nb < 2; ++nb) {
                uint32_t q[4];
                ldm4(q, bBase + nb * 16 * PADB + kc * 32);
                bh[2 * nb][0] = q[0]; bh[2 * nb][1] = q[2];
                bh[2 * nb + 1][0] = q[1]; bh[2 * nb + 1][1] = q[3];
                ldm4(q, bBase + TILE + nb * 16 * PADB + kc * 32);
                bl[2 * nb][0] = q[0]; bl[2 * nb][1] = q[2];
                bl[2 * nb + 1][0] = q[1]; bl[2 * nb + 1][1] = q[3];
            }
#pragma unroll
            for (int mc = 0; mc < 2; ++mc) {
                uint32_t ah[4], al[4];
                ldm4(ah, aBase + mc * 16 * PADB + kc * 32);
                ldm4(al, aBase + TILE + mc * 16 * PADB + kc * 32);
#pragma unroll
                for (int n8 = 0; n8 < 4; ++n8) {
                    mma16816(acc[mc][n8], ah, bh[n8]);
                    mma16816(acc[mc][n8], ah, bl[n8]);
                    mma16816(acc[mc][n8], al, bh[n8]);
                }
            }
        }

        // ---- epilogue: silu(out+b2)·w3, row-sum; quad shfl reduce ----
        float rs[2][2];
        rs[0][0] = rs[0][1] = rs[1][0] = rs[1][1] = 0.0f;
#pragma unroll
        for (int mc = 0; mc < 2; ++mc)
#pragma unroll
            for (int n8 = 0; n8 < 4; ++n8) {
                rs[mc][0] = fmaf(silu_f(acc[mc][n8][0] + b2v0[n8]), w3v0[n8], rs[mc][0]);
                rs[mc][0] = fmaf(silu_f(acc[mc][n8][1] + b2v1[n8]), w3v1[n8], rs[mc][0]);
                rs[mc][1] = fmaf(silu_f(acc[mc][n8][2] + b2v0[n8]), w3v0[n8], rs[mc][1]);
                rs[mc][1] = fmaf(silu_f(acc[mc][n8][3] + b2v1[n8]), w3v1[n8], rs[mc][1]);
            }
#pragma unroll
        for (int s = 1; s < 4; s <<= 1) {
#pragma unroll
            for (int mc = 0; mc < 2; ++mc) {
                rs[mc][0] += __shfl_xor_sync(0xffffffffu, rs[mc][0], s);
                rs[mc][1] += __shfl_xor_sync(0xffffffffu, rs[mc][1], s);
            }
        }
        if ((l & 3) == 0) {
            int rq = l >> 2;
#pragma unroll
            for (int mc = 0; mc < 2; ++mc) {
                S->predp[nq][mq * 32 + mc * 16 + rq]     = rs[mc][0];
                S->predp[nq][mq * 32 + mc * 16 + 8 + rq] = rs[mc][1];
            }
        }
        __syncthreads();

        // ---- x update ----
        if (tid < TM) {
            float p = S->predp[0][tid] + S->predp[1][tid]
                    + S->predp[2][tid] + S->predp[3][tid] + S->b3v;
            S->xs[tid] = (S->xs[tid] - S->cB[t] * p) * S->cA[t] + S->cC[t] * S->nzs[tid];
        }
        __syncthreads();
    }

    if (tid < TM)
        gout[rowBase + tid] = S->xs[tid];
}

extern "C" void kernel_launch(void* const* d_in, const int* in_sizes, int n_in,
                              void* d_out, int out_size)
{
    const float* ctx = (const float*)d_in[0];
    const float* x0  = (const float*)d_in[1];
    const float* nz  = (const float*)d_in[2];
    const float* W1  = (const float*)d_in[3];
    const float* b1  = (const float*)d_in[4];
    const float* W2  = (const float*)d_in[5];
    const float* b2  = (const float*)d_in[6];
    const float* W3  = (const float*)d_in[7];
    const float* b3  = (const float*)d_in[8];
    const float* te  = (const float*)d_in[9];
    float* out = (float*)d_out;

    const int B = in_sizes[1];
    const size_t smem = OFF_SMALL + sizeof(Small);   // ~146 KB

    cudaFuncSetAttribute(diff_kernel,
                         cudaFuncAttributeMaxDynamicSharedMemorySize,
                         (int)smem);

    diff_kernel<<<B / TM, NTH, smem>>>(ctx, x0, nz, W1, b1, W2, b2, W3, b3, te,
                                       out, B);
}

// round 9
// speedup vs baseline: 6.6216x; 1.9589x over previous
#include <cuda_runtime.h>
#include <cuda_fp16.h>
#include <cstdint>

#define D        128
#define TM       64              // rows per CTA (2 CTAs co-resident per SM)
#define NTH      256
#define TSTEPS   100

#define PADB     272             // bytes per fp16 tile row (136 h, ≡4 words mod 32)
#define TILE_A   (TM * PADB)     // 17408
#define TILE_B   (D * PADB)      // 34816

// ---- dynamic smem byte offsets (per CTA ~91KB -> 2 CTAs/SM) ----
#define OFF_C1    0                      // C1s [k=128][r=64] fp32, 32KB (ctx@W1+b1)
#define OFF_A     32768                  // h1 fp16 tile [m][k]
#define OFF_B     (OFF_A + TILE_A)       // W2^T fp16 tile [n][k]
#define OFF_SMALL (OFF_B + TILE_B)       // 84992

struct Small {
    float xs[TM];
    float nzs[TM];
    float w1x[D], w1t[D], b1s[D], b2s[D], w3s[D];
    float tembs[TSTEPS], cA[TSTEPS], cB[TSTEPS], cC[TSTEPS];
    float predp[4][TM];
    float b3v;
};

__device__ __forceinline__ uint32_t smem_u32(const void* p) {
    uint32_t a;
    asm("{ .reg .u64 t; cvta.to.shared.u64 t, %1; cvt.u32.u64 %0, t; }" : "=r"(a) : "l"(p));
    return a;
}
// silu = 0.5x + 0.5x*tanh(x/2): ONE MUFU
__device__ __forceinline__ float silu_f(float v) {
    float th, hv = 0.5f * v;
    asm("tanh.approx.f32 %0, %1;" : "=f"(th) : "f"(hv));
    return fmaf(hv, th, hv);
}
__device__ __forceinline__ void ldm4(uint32_t* r, uint32_t addr) {
    asm volatile("ldmatrix.sync.aligned.m8n8.x4.shared.b16 {%0,%1,%2,%3}, [%4];"
                 : "=r"(r[0]), "=r"(r[1]), "=r"(r[2]), "=r"(r[3]) : "r"(addr));
}
__device__ __forceinline__ void mma16816(float* c, const uint32_t* a, const uint32_t* b) {
    asm volatile(
        "mma.sync.aligned.m16n8k16.row.col.f32.f16.f16.f32 "
        "{%0,%1,%2,%3}, {%4,%5,%6,%7}, {%8,%9}, {%0,%1,%2,%3};"
        : "+f"(c[0]), "+f"(c[1]), "+f"(c[2]), "+f"(c[3])
        : "r"(a[0]), "r"(a[1]), "r"(a[2]), "r"(a[3]), "r"(b[0]), "r"(b[1]));
}

extern "C" __global__ void __launch_bounds__(NTH, 2)
diff_kernel(const float* __restrict__ gctx,
            const float* __restrict__ gx0,
            const float* __restrict__ gnoise,
            const float* __restrict__ gW1,
            const float* __restrict__ gb1,
            const float* __restrict__ gW2,
            const float* __restrict__ gb2,
            const float* __restrict__ gW3,
            const float* __restrict__ gb3,
            const float* __restrict__ gtemb,
            float* __restrict__ gout,
            int B)
{
    extern __shared__ char smb[];
    float* C1s = (float*)(smb + OFF_C1);
    Small* S   = (Small*)(smb + OFF_SMALL);

    const int tid = threadIdx.x;
    const int w   = tid >> 5;
    const int l   = tid & 31;
    const int rowBase = blockIdx.x * TM;

    // ---- stage ctx^T (fp32, 32KB) into A+B scratch; scalars ----
    float* ctxT = (float*)(smb + OFF_A);     // [d][r] 128x64 fp32
    if (tid < D) {
        S->w1x[tid] = gW1[D * D + tid];
        S->w1t[tid] = gW1[D * D + D + tid];
        S->b1s[tid] = gb1[tid];
        S->b2s[tid] = gb2[tid];
        S->w3s[tid] = gW3[tid];
        if (tid < TM) S->xs[tid] = gx0[rowBase + tid];
    } else if (tid < D + TSTEPS) {
        S->tembs[tid - D] = gtemb[tid - D];
    }
    if (tid == 0) {
        S->b3v = gb3[0];
        float acp = 1.0f;
        for (int t = 0; t < TSTEPS; ++t) {
            float beta  = 1e-4f + (0.02f - 1e-4f) * ((float)t * (1.0f / 99.0f));
            float alpha = 1.0f - beta;
            acp *= alpha;
            S->cA[t] = 1.0f / sqrtf(alpha);
            S->cB[t] = beta / sqrtf(1.0f - acp);
            S->cC[t] = (t > 0) ? sqrtf(beta) : 0.0f;
        }
    }
    for (int i = tid; i < D * TM / 4; i += NTH) {
        int r  = i >> 5;                // 0..63
        int d4 = (i & 31) << 2;         // 0,4,..,124
        float4 v = *(const float4*)&gctx[(size_t)(rowBase + r) * D + d4];
        ctxT[(d4 + 0) * TM + r] = v.x;
        ctxT[(d4 + 1) * TM + r] = v.y;
        ctxT[(d4 + 2) * TM + r] = v.z;
        ctxT[(d4 + 3) * TM + r] = v.w;
    }
    __syncthreads();

    // ---- prologue GEMM (once): C1s[j][r] = ctx@W1 + b1; W1 read via L1/L2 ----
    {
        const int j0 = (tid & 15) * 8;
        const int r0 = (tid >> 4) * 4;
        float acc[4][8];
#pragma unroll
        for (int a = 0; a < 4; ++a)
#pragma unroll
            for (int b = 0; b < 8; ++b) acc[a][b] = 0.0f;
#pragma unroll 4
        for (int d = 0; d < D; ++d) {
            float4 av4 = *(const float4*)&ctxT[d * TM + r0];
            float4 w0  = *(const float4*)&gW1[d * D + j0];
            float4 w1  = *(const float4*)&gW1[d * D + j0 + 4];
            float av[4] = {av4.x, av4.y, av4.z, av4.w};
            float bv[8] = {w0.x, w0.y, w0.z, w0.w, w1.x, w1.y, w1.z, w1.w};
#pragma unroll
            for (int a = 0; a < 4; ++a)
#pragma unroll
                for (int b = 0; b < 8; ++b)
                    acc[a][b] = fmaf(av[a], bv[b], acc[a][b]);
        }
        __syncthreads();                 // ctxT scratch no longer needed
#pragma unroll
        for (int b = 0; b < 8; ++b) {
            float bias = S->b1s[j0 + b];
#pragma unroll
            for (int a = 0; a < 4; ++a)
                C1s[(j0 + b) * TM + r0 + a] = acc[a][b] + bias;
        }
    }

    // ---- build B tile once: Bt[n][k] = W2[k][n] fp16, stride 272B ----
    for (int idx = tid; idx < D * D; idx += NTH) {
        int k = idx >> 7, n = idx & 127;
        *(__half*)(smb + OFF_B + n * PADB + k * 2) = __float2half_rn(gW2[idx]);
    }
    __syncthreads();

    // ---- per-thread roles ----
    // phase 1: 4 threads/row; thread owns row r1, k-range [kh, kh+32)
    const int r1  = tid & 63;
    const int kh  = (tid >> 6) << 5;          // 0,32,64,96 (warp-uniform)
    const int rot = l >> 3;                   // XOR rotation -> conflict-free stores
    char* At = smb + OFF_A;

    // phase 2: 2x4 warp grid, each warp 32 rows x 32 cols
    const int mq = w & 1;
    const int nq = w >> 1;
    const uint32_t aBase = smem_u32(smb + OFF_A)
                         + (uint32_t)(mq * 32 + (l & 15)) * PADB + (uint32_t)(l >> 4) * 16;
    const uint32_t bBase = smem_u32(smb + OFF_B)
                         + (uint32_t)(nq * 32 + (l & 15)) * PADB + (uint32_t)(l >> 4) * 16;

    // hoisted epilogue constants: cols c(n8) = nq*32 + n8*8 + (l%4)*2 + {0,1}
    float b2v0[4], b2v1[4], w3v0[4], w3v1[4];
#pragma unroll
    for (int n8 = 0; n8 < 4; ++n8) {
        int c = nq * 32 + n8 * 8 + (l & 3) * 2;
        b2v0[n8] = S->b2s[c];     b2v1[n8] = S->b2s[c + 1];
        w3v0[n8] = S->w3s[c];     w3v1[n8] = S->w3s[c + 1];
    }

    for (int it = 0; it < TSTEPS; ++it) {
        const int t = TSTEPS - 1 - it;
        const float temb = S->tembs[t];
        const float xr = S->xs[r1];

        // ---- phase 1: h1 = silu(C1 + x*w1x + temb*w1t) -> fp16 A tile ----
#pragma unroll 4
        for (int j = 0; j < 16; ++j) {
            int kp = j ^ rot;                  // permutation of 0..15, bank-conflict-free
            int k  = kh + kp * 2;
            float h0 = silu_f(fmaf(xr, S->w1x[k],     C1s[k * TM + r1])       + temb * S->w1t[k]);
            float h1 = silu_f(fmaf(xr, S->w1x[k + 1], C1s[(k + 1) * TM + r1]) + temb * S->w1t[k + 1]);
            *(__half2*)(At + r1 * PADB + k * 2) = __floats2half2_rn(h0, h1);
        }
        if (tid < TM)
            S->nzs[tid] = gnoise[(size_t)it * (size_t)B + rowBase + tid];
        __syncthreads();

        // ---- phase 2: out = A @ B^T  (fp16 HMMA, f32 accum) ----
        float acc[2][4][4];
#pragma unroll
        for (int mc = 0; mc < 2; ++mc)
#pragma unroll
            for (int n8 = 0; n8 < 4; ++n8)
#pragma unroll
                for (int q = 0; q < 4; ++q) acc[mc][n8][q] = 0.0f;

#pragma unroll
        for (int kc = 0; kc < 8; ++kc) {
            uint32_t bf[4][2];
#pragma unroll
            for (int nb = 0; nb < 2; ++nb) {
                uint32_t q[4];
                ldm4(q, bBase + nb * 16 * PADB + kc * 32);
                bf[2 * nb][0] = q[0];     bf[2 * nb][1] = q[2];
                bf[2 * nb + 1][0] = q[1]; bf[2 * nb + 1][1] = q[3];
            }
#pragma unroll
            for (int mc = 0; mc < 2; ++mc) {
                uint32_t af[4];
                ldm4(af, aBase + mc * 16 * PADB + kc * 32);
#pragma unroll
                for (int n8 = 0; n8 < 4; ++n8)
                    mma16816(acc[mc][n8], af, bf[n8]);
            }
        }

        // ---- epilogue: silu(out+b2)·w3 row-sum; quad shfl reduce ----
        float rs[2][2];
        rs[0][0] = rs[0][1] = rs[1][0] = rs[1][1] = 0.0f;
#pragma unroll
        for (int mc = 0; mc < 2; ++mc)
#pragma unroll
            for (int n8 = 0; n8 < 4; ++n8) {
                rs[mc][0] = fmaf(silu_f(acc[mc][n8][0] + b2v0[n8]), w3v0[n8], rs[mc][0]);
                rs[mc][0] = fmaf(silu_f(acc[mc][n8][1] + b2v1[n8]), w3v1[n8], rs[mc][0]);
                rs[mc][1] = fmaf(silu_f(acc[mc][n8][2] + b2v0[n8]), w3v0[n8], rs[mc][1]);
                rs[mc][1] = fmaf(silu_f(acc[mc][n8][3] + b2v1[n8]), w3v1[n8], rs[mc][1]);
            }
#pragma unroll
        for (int s = 1; s < 4; s <<= 1) {
#pragma unroll
            for (int mc = 0; mc < 2; ++mc) {
                rs[mc][0] += __shfl_xor_sync(0xffffffffu, rs[mc][0], s);
                rs[mc][1] += __shfl_xor_sync(0xffffffffu, rs[mc][1], s);
            }
        }
        if ((l & 3) == 0) {
            int rq = l >> 2;
#pragma unroll
            for (int mc = 0; mc < 2; ++mc) {
                S->predp[nq][mq * 32 + mc * 16 + rq]     = rs[mc][0];
                S->predp[nq][mq * 32 + mc * 16 + 8 + rq] = rs[mc][1];
            }
        }
        __syncthreads();

        // ---- x update ----
        if (tid < TM) {
            float p = S->predp[0][tid] + S->predp[1][tid]
                    + S->predp[2][tid] + S->predp[3][tid] + S->b3v;
            S->xs[tid] = (S->xs[tid] - S->cB[t] * p) * S->cA[t] + S->cC[t] * S->nzs[tid];
        }
        __syncthreads();
    }

    if (tid < TM)
        gout[rowBase + tid] = S->xs[tid];
}

extern "C" void kernel_launch(void* const* d_in, const int* in_sizes, int n_in,
                              void* d_out, int out_size)
{
    const float* ctx = (const float*)d_in[0];
    const float* x0  = (const float*)d_in[1];
    const float* nz  = (const float*)d_in[2];
    const float* W1  = (const float*)d_in[3];
    const float* b1  = (const float*)d_in[4];
    const float* W2  = (const float*)d_in[5];
    const float* b2  = (const float*)d_in[6];
    const float* W3  = (const float*)d_in[7];
    const float* b3  = (const float*)d_in[8];
    const float* te  = (const float*)d_in[9];
    float* out = (float*)d_out;

    const int B = in_sizes[1];
    const size_t smem = OFF_SMALL + sizeof(Small);   // ~91 KB -> 2 CTAs/SM

    cudaFuncSetAttribute(diff_kernel,
                         cudaFuncAttributeMaxDynamicSharedMemorySize,
                         (int)smem);

    diff_kernel<<<B / TM, NTH, smem>>>(ctx, x0, nz, W1, b1, W2, b2, W3, b3, te,
                                       out, B);
}

// round 10
// speedup vs baseline: 6.9423x; 1.0484x over previous
#include <cuda_runtime.h>
#include <cuda_fp16.h>
#include <cstdint>

#define D        128
#define TM       32              // rows per CTA (4 CTAs co-resident per SM)
#define NTH      128
#define TSTEPS   100

#define PADB     272             // bytes per fp16 tile row (136 h, ≡4 words mod 32)
#define TILE_A   (TM * PADB)     // 8704
#define TILE_B   (D * PADB)      // 34816

// ---- dynamic smem byte offsets (per CTA ~54KB -> 4 CTAs/SM) ----
#define OFF_C1H   0                      // C1 as half2: [kp=64][r=32], 8KB
#define OFF_A     8192                   // h1 fp16 tile [m][k]
#define OFF_B     (OFF_A + TILE_A)       // W2^T fp16 tile [n][k]  (16896)
#define OFF_SMALL (OFF_B + TILE_B)       // 51712

struct Small {
    float xs[TM];
    float nzs[TM];
    float w1x[D], w1t[D], b1s[D], b2s[D], w3s[D];
    float tembs[TSTEPS];
    float predp[4][TM];
    float b3v;
};

__device__ __forceinline__ uint32_t smem_u32(const void* p) {
    uint32_t a;
    asm("{ .reg .u64 t; cvta.to.shared.u64 t, %1; cvt.u32.u64 %0, t; }" : "=r"(a) : "l"(p));
    return a;
}
// silu = 0.5x + 0.5x*tanh(x/2): ONE MUFU
__device__ __forceinline__ float silu_f(float v) {
    float th, hv = 0.5f * v;
    asm("tanh.approx.f32 %0, %1;" : "=f"(th) : "f"(hv));
    return fmaf(hv, th, hv);
}
__device__ __forceinline__ void ldm4(uint32_t* r, uint32_t addr) {
    asm volatile("ldmatrix.sync.aligned.m8n8.x4.shared.b16 {%0,%1,%2,%3}, [%4];"
                 : "=r"(r[0]), "=r"(r[1]), "=r"(r[2]), "=r"(r[3]) : "r"(addr));
}
__device__ __forceinline__ void mma16816(float* c, const uint32_t* a, const uint32_t* b) {
    asm volatile(
        "mma.sync.aligned.m16n8k16.row.col.f32.f16.f16.f32 "
        "{%0,%1,%2,%3}, {%4,%5,%6,%7}, {%8,%9}, {%0,%1,%2,%3};"
        : "+f"(c[0]), "+f"(c[1]), "+f"(c[2]), "+f"(c[3])
        : "r"(a[0]), "r"(a[1]), "r"(a[2]), "r"(a[3]), "r"(b[0]), "r"(b[1]));
}

extern "C" __global__ void __launch_bounds__(NTH, 4)
diff_kernel(const float* __restrict__ gctx,
            const float* __restrict__ gx0,
            const float* __restrict__ gnoise,
            const float* __restrict__ gW1,
            const float* __restrict__ gb1,
            const float* __restrict__ gW2,
            const float* __restrict__ gb2,
            const float* __restrict__ gW3,
            const float* __restrict__ gb3,
            const float* __restrict__ gtemb,
            float* __restrict__ gout,
            int B)
{
    extern __shared__ char smb[];
    __half2* C1h = (__half2*)(smb + OFF_C1H);   // [kp][r]
    Small*   S   = (Small*)(smb + OFF_SMALL);

    const int tid = threadIdx.x;
    const int w   = tid >> 5;
    const int l   = tid & 31;
    const int rowBase = blockIdx.x * TM;

    // ---- scalars + ctx^T staging (fp32 scratch spans A + part of B region) ----
    float* ctxT = (float*)(smb + OFF_A);        // [d][r] 128x32 fp32 = 16KB
    S->w1x[tid] = gW1[D * D + tid];
    S->w1t[tid] = gW1[D * D + D + tid];
    S->b1s[tid] = gb1[tid];
    S->b2s[tid] = gb2[tid];
    S->w3s[tid] = gW3[tid];
    if (tid < TM)     S->xs[tid]    = gx0[rowBase + tid];
    if (tid < TSTEPS) S->tembs[tid] = gtemb[tid];
    if (tid == 0)     S->b3v = gb3[0];
    for (int i = tid; i < D * TM / 4; i += NTH) {
        int r  = i >> 5;                 // 0..31
        int d4 = (i & 31) << 2;          // 0,4,..,124
        float4 v = *(const float4*)&gctx[(size_t)(rowBase + r) * D + d4];
        ctxT[(d4 + 0) * TM + r] = v.x;
        ctxT[(d4 + 1) * TM + r] = v.y;
        ctxT[(d4 + 2) * TM + r] = v.z;
        ctxT[(d4 + 3) * TM + r] = v.w;
    }
    __syncthreads();

    // ---- prologue GEMM (once): acc = ctx@W1; W1 via L2 ----
    float pacc[4][8];
    {
        const int j0 = (tid & 15) * 8;
        const int r0 = (tid >> 4) * 4;
#pragma unroll
        for (int a = 0; a < 4; ++a)
#pragma unroll
            for (int b = 0; b < 8; ++b) pacc[a][b] = 0.0f;
#pragma unroll 4
        for (int d = 0; d < D; ++d) {
            float4 av4 = *(const float4*)&ctxT[d * TM + r0];
            float4 w0  = *(const float4*)&gW1[d * D + j0];
            float4 w1  = *(const float4*)&gW1[d * D + j0 + 4];
            float av[4] = {av4.x, av4.y, av4.z, av4.w};
            float bv[8] = {w0.x, w0.y, w0.z, w0.w, w1.x, w1.y, w1.z, w1.w};
#pragma unroll
            for (int a = 0; a < 4; ++a)
#pragma unroll
                for (int b = 0; b < 8; ++b)
                    pacc[a][b] = fmaf(av[a], bv[b], pacc[a][b]);
        }
        __syncthreads();                 // all ctxT reads done; scratch reusable

        // store C1 as half2 k-pairs: C1h[kp][r]
#pragma unroll
        for (int p = 0; p < 4; ++p) {
            int j  = j0 + 2 * p;
            int kp = j >> 1;
            float bz0 = S->b1s[j], bz1 = S->b1s[j + 1];
#pragma unroll
            for (int a = 0; a < 4; ++a)
                C1h[kp * TM + r0 + a] =
                    __floats2half2_rn(pacc[a][2 * p] + bz0, pacc[a][2 * p + 1] + bz1);
        }
    }

    // ---- build B tile once: Bt[n][k] = W2[k][n] fp16, stride 272B ----
    for (int idx = tid; idx < D * D; idx += NTH) {
        int k = idx >> 7, n = idx & 127;
        *(__half*)(smb + OFF_B + n * PADB + k * 2) = __float2half_rn(gW2[idx]);
    }

    // running cumprod: start at acp_99, divide down each step
    float acp = 1.0f;
#pragma unroll 4
    for (int t = 0; t < TSTEPS; ++t)
        acp *= 1.0f - (1e-4f + (0.02f - 1e-4f) * ((float)t * (1.0f / 99.0f)));
    __syncthreads();

    // ---- per-thread roles ----
    // phase 1: lane = row; warp owns k-range [32w, 32w+32)
    const int r1  = l;
    const int khp = w << 4;                  // k-pair base: 0,16,32,48
    const int rot = l >> 3;
    char* At = smb + OFF_A;

    // phase 2: warp w covers rows 0..31 x cols [32w, 32w+32)
    const int nq = w;
    const uint32_t aBase = smem_u32(smb + OFF_A)
                         + (uint32_t)(l & 15) * PADB + (uint32_t)(l >> 4) * 16;
    const uint32_t bBase = smem_u32(smb + OFF_B)
                         + (uint32_t)(nq * 32 + (l & 15)) * PADB + (uint32_t)(l >> 4) * 16;

    // hoisted epilogue constants: cols c(n8) = nq*32 + n8*8 + (l%4)*2 + {0,1}
    float b2v0[4], b2v1[4], w3v0[4], w3v1[4];
#pragma unroll
    for (int n8 = 0; n8 < 4; ++n8) {
        int c = nq * 32 + n8 * 8 + (l & 3) * 2;
        b2v0[n8] = S->b2s[c];     b2v1[n8] = S->b2s[c + 1];
        w3v0[n8] = S->w3s[c];     w3v1[n8] = S->w3s[c + 1];
    }

    for (int it = 0; it < TSTEPS; ++it) {
        const int t = TSTEPS - 1 - it;
        const float temb  = S->tembs[t];
        const float beta  = 1e-4f + (0.02f - 1e-4f) * ((float)t * (1.0f / 99.0f));
        const float alpha = 1.0f - beta;
        const float cAv   = 1.0f / sqrtf(alpha);
        const float cBv   = beta / sqrtf(1.0f - acp);
        const float cCv   = (t > 0) ? sqrtf(beta) : 0.0f;
        const float xr    = S->xs[r1];

        // ---- phase 1: h1 = silu(C1 + x*w1x + temb*w1t) -> fp16 A tile ----
#pragma unroll 4
        for (int j = 0; j < 16; ++j) {
            int kpg = khp + (j ^ rot);           // k-pair index 0..63
            int k   = kpg * 2;
            float2 c = __half22float2(C1h[kpg * TM + r1]);
            float h0 = silu_f(fmaf(xr, S->w1x[k],     c.x) + temb * S->w1t[k]);
            float h1 = silu_f(fmaf(xr, S->w1x[k + 1], c.y) + temb * S->w1t[k + 1]);
            *(__half2*)(At + r1 * PADB + kpg * 4) = __floats2half2_rn(h0, h1);
        }
        if (tid < TM)
            S->nzs[tid] = gnoise[(size_t)it * (size_t)B + rowBase + tid];
        __syncthreads();

        // ---- phase 2: out = A @ B^T  (fp16 HMMA, f32 accum) ----
        float acc[2][4][4];
#pragma unroll
        for (int mc = 0; mc < 2; ++mc)
#pragma unroll
            for (int n8 = 0; n8 < 4; ++n8)
#pragma unroll
                for (int q = 0; q < 4; ++q) acc[mc][n8][q] = 0.0f;

#pragma unroll
        for (int kc = 0; kc < 8; ++kc) {
            uint32_t bf[4][2];
#pragma unroll
            for (int nb = 0; nb < 2; ++nb) {
                uint32_t q[4];
                ldm4(q, bBase + nb * 16 * PADB + kc * 32);
                bf[2 * nb][0] = q[0];     bf[2 * nb][1] = q[2];
                bf[2 * nb + 1][0] = q[1]; bf[2 * nb + 1][1] = q[3];
            }
#pragma unroll
            for (int mc = 0; mc < 2; ++mc) {
                uint32_t af[4];
                ldm4(af, aBase + mc * 16 * PADB + kc * 32);
#pragma unroll
                for (int n8 = 0; n8 < 4; ++n8)
                    mma16816(acc[mc][n8], af, bf[n8]);
            }
        }

        // ---- epilogue: silu(out+b2)·w3 row-sum; quad shfl reduce ----
        float rs[2][2];
        rs[0][0] = rs[0][1] = rs[1][0] = rs[1][1] = 0.0f;
#pragma unroll
        for (int mc = 0; mc < 2; ++mc)
#pragma unroll
            for (int n8 = 0; n8 < 4; ++n8) {
                rs[mc][0] = fmaf(silu_f(acc[mc][n8][0] + b2v0[n8]), w3v0[n8], rs[mc][0]);
                rs[mc][0] = fmaf(silu_f(acc[mc][n8][1] + b2v1[n8]), w3v1[n8], rs[mc][0]);
                rs[mc][1] = fmaf(silu_f(acc[mc][n8][2] + b2v0[n8]), w3v0[n8], rs[mc][1]);
                rs[mc][1] = fmaf(silu_f(acc[mc][n8][3] + b2v1[n8]), w3v1[n8], rs[mc][1]);
            }
#pragma unroll
        for (int s = 1; s < 4; s <<= 1) {
#pragma unroll
            for (int mc = 0; mc < 2; ++mc) {
                rs[mc][0] += __shfl_xor_sync(0xffffffffu, rs[mc][0], s);
                rs[mc][1] += __shfl_xor_sync(0xffffffffu, rs[mc][1], s);
            }
        }
        if ((l & 3) == 0) {
            int rq = l >> 2;
#pragma unroll
            for (int mc = 0; mc < 2; ++mc) {
                S->predp[nq][mc * 16 + rq]     = rs[mc][0];
                S->predp[nq][mc * 16 + 8 + rq] = rs[mc][1];
            }
        }
        __syncthreads();

        // ---- x update ----
        if (tid < TM) {
            float p = S->predp[0][tid] + S->predp[1][tid]
                    + S->predp[2][tid] + S->predp[3][tid] + S->b3v;
            S->xs[tid] = (S->xs[tid] - cBv * p) * cAv + cCv * S->nzs[tid];
        }
        acp /= alpha;                       // acp_{t-1} for next iteration
        __syncthreads();
    }

    if (tid < TM)
        gout[rowBase + tid] = S->xs[tid];
}

extern "C" void kernel_launch(void* const* d_in, const int* in_sizes, int n_in,
                              void* d_out, int out_size)
{
    const float* ctx = (const float*)d_in[0];
    const float* x0  = (const float*)d_in[1];
    const float* nz  = (const float*)d_in[2];
    const float* W1  = (const float*)d_in[3];
    const float* b1  = (const float*)d_in[4];
    const float* W2  = (const float*)d_in[5];
    const float* b2  = (const float*)d_in[6];
    const float* W3  = (const float*)d_in[7];
    const float* b3  = (const float*)d_in[8];
    const float* te  = (const float*)d_in[9];
    float* out = (float*)d_out;

    const int B = in_sizes[1];
    const size_t smem = OFF_SMALL + sizeof(Small);   // ~54.2 KB -> 4 CTAs/SM

    cudaFuncSetAttribute(diff_kernel,
                         cudaFuncAttributeMaxDynamicSharedMemorySize,
                         (int)smem);

    diff_kernel<<<B / TM, NTH, smem>>>(ctx, x0, nz, W1, b1, W2, b2, W3, b3, te,
                                       out, B);
}